// round 3
// baseline (speedup 1.0000x reference)
#include <cuda_runtime.h>

// ---------------------------------------------------------------------------
// GAT collapses (uniform per-item node features + per-dst softmax weights that
// sum to 1 thanks to self-loops) => the whole model is a 7-layer MLP on 64 rows.
// One persistent kernel, 64 blocks x 512 threads (4 warps/SMSP), outputs
// partitioned across blocks, 6 release/acquire grid barriers, activations
// staged in smem per layer, f32x2 FFMA2 dot products.
// ---------------------------------------------------------------------------

typedef unsigned long long ULL;

__device__ __forceinline__ void ffma2(ULL& d, ULL a, ULL b) {
    asm("fma.rn.f32x2 %0, %1, %2, %0;" : "+l"(d) : "l"(a), "l"(b));
}
__device__ __forceinline__ float2 unpack2f(ULL v) {
    float2 f; asm("mov.b64 {%0, %1}, %2;" : "=f"(f.x), "=f"(f.y) : "l"(v)); return f;
}

// Ping-pong activation buffers: k-major [k4][64 rows] float4.
__device__ __align__(16) float4 gA[80 * 64];
__device__ __align__(16) float4 gB[80 * 64];
// Monotonic barrier counters (never reset; safe across graph replays).
__device__ int g_bar[8];

#define NBLK 64

__device__ __forceinline__ void gbar(int idx) {
    __syncthreads();
    if (threadIdx.x == 0) {
        int old;
        asm volatile("atom.release.gpu.global.add.s32 %0, [%1], 1;"
                     : "=r"(old) : "l"(g_bar + idx) : "memory");
        int target = old - (old & (NBLK - 1)) + NBLK;
        int cur;
        do {
            asm volatile("ld.acquire.gpu.global.s32 %0, [%1];"
                         : "=r"(cur) : "l"(g_bar + idx) : "memory");
        } while (cur < target);
    }
    __syncthreads();
}

// K-dim dot, thread covers half of K (kh = 0/1) for row r; acts in smem.
template<int K>
__device__ __forceinline__ float dotK(const float* __restrict__ Wrow,
                                      const float4* __restrict__ sAct,
                                      int r, int kh) {
    const longlong2* wp = (const longlong2*)(Wrow + kh * (K / 2));
    const longlong2* ap = (const longlong2*)(sAct + (kh * (K / 8)) * 16 + r);
    ULL a0 = 0ull, a1 = 0ull;
    #pragma unroll 8
    for (int i = 0; i < K / 8; i++) {
        longlong2 w = wp[i];           // warp-broadcast (same o across lanes)
        longlong2 a = ap[(size_t)i * 16];
        ffma2(a0, (ULL)w.x, (ULL)a.x);
        ffma2(a1, (ULL)w.y, (ULL)a.y);
    }
    float2 f0 = unpack2f(a0), f1 = unpack2f(a1);
    return (f0.x + f0.y) + (f1.x + f1.y);
}

// Cooperative copy: KQ quads x 16 rows of this row-group from gIN into smem.
template<int KQ>
__device__ __forceinline__ void stage(const float4* __restrict__ gIN,
                                      float4* __restrict__ sAct, int g, int t) {
    #pragma unroll
    for (int i = t; i < KQ * 16; i += 512) {
        int q = i >> 4, r = i & 15;
        sAct[i] = gIN[q * 64 + g * 16 + r];
    }
}

__global__ __launch_bounds__(512, 1) void net_kernel(
    const float* __restrict__ x, const int* __restrict__ cidx,
    const float* __restrict__ W_in, const float* __restrict__ b_in,
    const float* __restrict__ gat_W, const float* __restrict__ gat_b,
    const float* __restrict__ emb,
    const float* __restrict__ W_fuse, const float* __restrict__ b_fuse,
    const float* __restrict__ W_p1, const float* __restrict__ b_p1,
    const float* __restrict__ W_p2, const float* __restrict__ b_p2,
    const float* __restrict__ W_p3, const float* __restrict__ b_p3,
    const float* __restrict__ W_d1, const float* __restrict__ b_d1,
    const float* __restrict__ W_d2, const float* __restrict__ b_d2,
    const float* __restrict__ W_d3, const float* __restrict__ b_d3,
    float* __restrict__ out) {

    __shared__ __align__(16) float4 sAct[80 * 16];   // 20 KB
    __shared__ __align__(16) float  sB[256];         // per-row tail input
    __shared__ float p2s[64], d2s[64];

    const int t    = threadIdx.x;
    const int bx   = blockIdx.x;
    const int g    = bx >> 4;         // row group 0..3 (16 rows)
    const int slice= bx & 15;         // 16-out slice
    const int w    = t >> 5;          // warp 0..15
    const int lane = t & 31;
    const int r    = lane & 15;       // local row
    const int kh   = lane >> 4;       // K half
    const int o    = slice * 16 + w;  // output feature 0..255

    float* Af = (float*)gA;
    float* Bf = (float*)gB;

    // ---- L0: relu(W_in x + b_in), K=64; x staged directly (no barrier) ----
    if (t < 256) {
        int q = t >> 4, rr = t & 15;
        sAct[t] = ((const float4*)x)[(g * 16 + rr) * 16 + q];
    }
    __syncthreads();
    {
        float s = dotK<64>(W_in + o * 64, sAct, r, kh);
        s += __shfl_xor_sync(0xffffffffu, s, 16);
        if (lane < 16)
            Af[((o >> 2) * 64 + g * 16 + r) * 4 + (o & 3)] = fmaxf(s + b_in[o], 0.f);
    }
    gbar(0);

    // ---- L1..L3: collapsed GAT layers [256 x 256] ----
    {
        stage<64>(gA, sAct, g, t);
        __syncthreads();
        float s = dotK<256>(gat_W + o * 256, sAct, r, kh);
        s += __shfl_xor_sync(0xffffffffu, s, 16);
        if (lane < 16)
            Bf[((o >> 2) * 64 + g * 16 + r) * 4 + (o & 3)] = fmaxf(s + gat_b[o], 0.f);
    }
    gbar(1);
    {
        stage<64>(gB, sAct, g, t);
        __syncthreads();
        float s = dotK<256>(gat_W + 65536 + o * 256, sAct, r, kh);
        s += __shfl_xor_sync(0xffffffffu, s, 16);
        if (lane < 16)
            Af[((o >> 2) * 64 + g * 16 + r) * 4 + (o & 3)] = fmaxf(s + gat_b[256 + o], 0.f);
    }
    gbar(2);
    {
        stage<64>(gA, sAct, g, t);
        __syncthreads();
        float s = dotK<256>(gat_W + 131072 + o * 256, sAct, r, kh);
        s += __shfl_xor_sync(0xffffffffu, s, 16);
        if (lane < 16)
            Bf[((o >> 2) * 64 + g * 16 + r) * 4 + (o & 3)] = fmaxf(s + gat_b[512 + o], 0.f);
    }
    gbar(3);

    // ---- L4: fuse [256 x 320] over [g3 ; emb[cidx]] ----
    {
        stage<64>(gB, sAct, g, t);
        if (t < 256) {                       // emb gather -> quads 64..79
            int q = t >> 4, rr = t & 15;
            int ci = cidx[g * 16 + rr];
            sAct[(64 + q) * 16 + rr] = ((const float4*)emb)[ci * 16 + q];
        }
        __syncthreads();
        float s = dotK<320>(W_fuse + o * 320, sAct, r, kh);
        s += __shfl_xor_sync(0xffffffffu, s, 16);
        if (lane < 16)
            Af[((o >> 2) * 64 + g * 16 + r) * 4 + (o & 3)] = fmaxf(s + b_fuse[o], 0.f);
    }
    gbar(4);

    // ---- L5: heads stage1 [p1 ; d1] = [256 x 256] ----
    {
        stage<64>(gA, sAct, g, t);
        __syncthreads();
        const float* Wp = (o < 128) ? (W_p1 + o * 256) : (W_d1 + (o - 128) * 256);
        float bb        = (o < 128) ? b_p1[o] : b_d1[o - 128];
        float s = dotK<256>(Wp, sAct, r, kh);
        s += __shfl_xor_sync(0xffffffffu, s, 16);
        if (lane < 16)
            Bf[((o >> 2) * 64 + g * 16 + r) * 4 + (o & 3)] = fmaxf(s + bb, 0.f);
    }
    gbar(5);

    // ---- Tail: block bx owns batch row bx; p2/d2 + final dots, no barriers ----
    {
        if (t < 64) sB[t * 4 + 0] = 0.f;  // (placeholder slot; overwritten below)
        if (t < 64) ((float4*)sB)[t] = gB[t * 64 + bx];
        __syncthreads();

        // p2 (warps 0..7) / d2 (warps 8..15): 8 outs per warp, K=128, lane = K/32
        {
            bool is_d = (w >= 8);
            int obase = (w & 7) * 8;
            const float* W2 = is_d ? W_d2 : W_p2;
            const float* b2 = is_d ? b_d2 : b_p2;
            const float* in = sB + (is_d ? 128 : 0);
            float4 av = ((const float4*)in)[lane];
            float acc[8];
            #pragma unroll
            for (int j = 0; j < 8; j++) {
                float4 wv = ((const float4*)(W2 + (obase + j) * 128))[lane];
                acc[j] = wv.x * av.x + wv.y * av.y + wv.z * av.z + wv.w * av.w;
            }
            #pragma unroll
            for (int m = 16; m >= 1; m >>= 1)
                #pragma unroll
                for (int j = 0; j < 8; j++)
                    acc[j] += __shfl_xor_sync(0xffffffffu, acc[j], m);
            if (lane < 8) {
                float v = 0.f;
                #pragma unroll
                for (int j = 0; j < 8; j++) if (lane == j) v = acc[j];
                int oo = obase + lane;
                v = fmaxf(v + b2[oo], 0.f);
                if (is_d) d2s[oo] = v; else p2s[oo] = v;
            }
        }
        __syncthreads();

        if (w == 0) {
            float s = W_p3[lane] * p2s[lane] + W_p3[lane + 32] * p2s[lane + 32];
            #pragma unroll
            for (int m = 16; m >= 1; m >>= 1) s += __shfl_xor_sync(0xffffffffu, s, m);
            if (lane == 0) out[bx] = s + b_p3[0];
        } else if (w == 1) {
            float s = W_d3[lane] * d2s[lane] + W_d3[lane + 32] * d2s[lane + 32];
            #pragma unroll
            for (int m = 16; m >= 1; m >>= 1) s += __shfl_xor_sync(0xffffffffu, s, m);
            if (lane == 0) out[64 + bx] = 1.f / (1.f + __expf(-(s + b_d3[0])));
        }
    }
}

extern "C" void kernel_launch(void* const* d_in, const int* in_sizes, int n_in,
                              void* d_out, int out_size) {
    const float* x      = (const float*)d_in[0];
    const int*   cidx   = (const int*)  d_in[1];
    // d_in[2] edge_index, d_in[3] edge_attr: unused (softmax collapse)
    const float* W_in   = (const float*)d_in[4];
    const float* b_in   = (const float*)d_in[5];
    const float* gat_W  = (const float*)d_in[6];
    // d_in[7..10]: attention params — unused (collapse)
    const float* gat_b  = (const float*)d_in[11];
    const float* emb    = (const float*)d_in[12];
    const float* W_fuse = (const float*)d_in[13];
    const float* b_fuse = (const float*)d_in[14];
    const float* W_p1   = (const float*)d_in[15];
    const float* b_p1   = (const float*)d_in[16];
    const float* W_p2   = (const float*)d_in[17];
    const float* b_p2   = (const float*)d_in[18];
    const float* W_p3   = (const float*)d_in[19];
    const float* b_p3   = (const float*)d_in[20];
    const float* W_d1   = (const float*)d_in[21];
    const float* b_d1   = (const float*)d_in[22];
    const float* W_d2   = (const float*)d_in[23];
    const float* b_d2   = (const float*)d_in[24];
    const float* W_d3   = (const float*)d_in[25];
    const float* b_d3   = (const float*)d_in[26];

    net_kernel<<<NBLK, 512>>>(x, cidx, W_in, b_in, gat_W, gat_b, emb,
                              W_fuse, b_fuse, W_p1, b_p1, W_p2, b_p2,
                              W_p3, b_p3, W_d1, b_d1, W_d2, b_d2,
                              W_d3, b_d3, (float*)d_out);
}